// round 13
// baseline (speedup 1.0000x reference)
#include <cuda_runtime.h>
#include <cuda_fp16.h>
#include <math.h>

#define NN 50000
#define NE 800000
#define D 128
#define NB 196      // (NN + 255) / 256
#define PAD 64      // padded CSR slots per node; P(deg>=64)~1e-21 for Poisson(16)

// ---------------- device scratch (no allocations allowed) ----------------
__device__ int            g_cnt[NN];        // in-degree cursor -> final in-degree
__device__ int            g_deg_out[NN];
__device__ unsigned short g_colp[NN * PAD]; // padded adjacency, uint16 (NN < 65536)
__device__ float          g_invd1[NN];
__device__ float          g_innorm[NN];
__device__ float          g_outnorm[NN];
__device__ __half         g_t [NN * D];
__device__ __half         g_y1[NN * D];
__device__ __half         g_y2[NN * D];
__device__ float          g_Wt[D * D];
__device__ __half         g_WhT[D * D];     // Wc transposed, fp16: [n][k]
__device__ float          g_bt[D];
__device__ float          g_bw[D];

__device__ __forceinline__ void add_h8(float* a, uint4 v) {
    __half2* h = (__half2*)&v;
    #pragma unroll
    for (int i = 0; i < 4; i++) {
        float2 f = __half22float2(h[i]);
        a[2 * i]     += f.x;
        a[2 * i + 1] += f.y;
    }
}
__device__ __forceinline__ unsigned f2_to_h2u(float2 f) {
    __half2 h = __floats2half2_rn(f.x, f.y);
    return *(unsigned*)&h;
}

// ---------------- graph preprocessing (worker stream) ----------------
// direct padded scatter (uint16 indices) + out-degree histogram
__global__ void k_scatter(const int* __restrict__ src, const int* __restrict__ dst) {
    int i = blockIdx.x * blockDim.x + threadIdx.x;
    if (i < NE / 2) {
        int2 s = __ldg(&((const int2*)src)[i]);
        int2 d = __ldg(&((const int2*)dst)[i]);
        int p0 = atomicAdd(&g_cnt[d.x], 1);
        g_colp[d.x * PAD + p0] = (unsigned short)s.x;
        int p1 = atomicAdd(&g_cnt[d.y], 1);
        g_colp[d.y * PAD + p1] = (unsigned short)s.y;
        atomicAdd(&g_deg_out[s.x], 1);
        atomicAdd(&g_deg_out[s.y], 1);
    }
}

__global__ void k_norms() {
    int i = blockIdx.x * blockDim.x + threadIdx.x;
    if (i < NN) {
        int di = g_cnt[i], dq = g_deg_out[i];
        g_invd1[i]   = 1.0f / (float)(di + 1);
        g_innorm[i]  = rsqrtf((float)(di > 0 ? di : 1));
        g_outnorm[i] = rsqrtf((float)(dq > 0 ? dq : 1));
    }
}

// ---------------- fused weight precompute (k-split, 512 threads/block) ----------------
__global__ __launch_bounds__(512) void k_wA(const float* __restrict__ W1,
                                            const float* __restrict__ b1,
                                            const float* __restrict__ W2,
                                            const float* __restrict__ b2) {
    int r = blockIdx.x;
    int c = threadIdx.x & 127;
    int ks = threadIdx.x >> 7;            // 0..3
    __shared__ float arow[D];
    __shared__ float part[4][D];
    if (threadIdx.x < D) arow[threadIdx.x] = (r < D) ? W1[r * D + threadIdx.x] : b1[threadIdx.x];
    __syncthreads();
    int k0 = ks * 32;
    float a0 = 0.f, a1 = 0.f, a2 = 0.f, a3 = 0.f;
    #pragma unroll
    for (int k = 0; k < 32; k += 4) {
        a0 += arow[k0 + k + 0] * __ldg(&W2[(k0 + k + 0) * D + c]);
        a1 += arow[k0 + k + 1] * __ldg(&W2[(k0 + k + 1) * D + c]);
        a2 += arow[k0 + k + 2] * __ldg(&W2[(k0 + k + 2) * D + c]);
        a3 += arow[k0 + k + 3] * __ldg(&W2[(k0 + k + 3) * D + c]);
    }
    part[ks][c] = (a0 + a1) + (a2 + a3);
    __syncthreads();
    if (ks == 0) {
        float acc = (part[0][c] + part[1][c]) + (part[2][c] + part[3][c]);
        if (r < D) g_Wt[r * D + c] = acc;
        else       g_bt[c] = acc + b2[c];
    }
}
__global__ __launch_bounds__(512) void k_wB(const float* __restrict__ W3) {
    int r = blockIdx.x;
    int c = threadIdx.x & 127;
    int ks = threadIdx.x >> 7;
    __shared__ float arow[D];
    __shared__ float part[4][D];
    if (threadIdx.x < D) arow[threadIdx.x] = (r < D) ? g_Wt[r * D + threadIdx.x] : g_bt[threadIdx.x];
    __syncthreads();
    int k0 = ks * 32;
    float a0 = 0.f, a1 = 0.f, a2 = 0.f, a3 = 0.f;
    #pragma unroll
    for (int k = 0; k < 32; k += 4) {
        a0 += arow[k0 + k + 0] * __ldg(&W3[(k0 + k + 0) * D + c]);
        a1 += arow[k0 + k + 1] * __ldg(&W3[(k0 + k + 1) * D + c]);
        a2 += arow[k0 + k + 2] * __ldg(&W3[(k0 + k + 2) * D + c]);
        a3 += arow[k0 + k + 3] * __ldg(&W3[(k0 + k + 3) * D + c]);
    }
    part[ks][c] = (a0 + a1) + (a2 + a3);
    __syncthreads();
    if (ks == 0) {
        float acc = (part[0][c] + part[1][c]) + (part[2][c] + part[3][c]);
        if (r < D) g_WhT[c * D + r] = __float2half(acc);
        else       g_bw[c] = acc;
    }
}

// ---------------- front GEMM via HMMA: g_t = fp16(x) @ Wc  (fp32 accum, fp16 out) -------
__global__ __launch_bounds__(256) void k_gemm(const float* __restrict__ x) {
    int warp = (blockIdx.x * 256 + threadIdx.x) >> 5;
    int lane = threadIdx.x & 31;
    int r0 = warp * 16;
    if (r0 >= NN) return;
    int g = lane >> 2, t4 = lane & 3;

    const float2* x2 = (const float2*)x;   // row = 64 float2

    float acc[16][4];
    #pragma unroll
    for (int nt = 0; nt < 16; nt++)
        #pragma unroll
        for (int j = 0; j < 4; j++) acc[nt][j] = 0.f;

    #pragma unroll
    for (int kt = 0; kt < 8; kt++) {
        int k0 = kt * 16;
        unsigned A0 = f2_to_h2u(__ldg(&x2[(size_t)(r0 + g)     * 64 + ((k0      + t4 * 2) >> 1)]));
        unsigned A1 = f2_to_h2u(__ldg(&x2[(size_t)(r0 + g + 8) * 64 + ((k0      + t4 * 2) >> 1)]));
        unsigned A2 = f2_to_h2u(__ldg(&x2[(size_t)(r0 + g)     * 64 + ((k0 + 8  + t4 * 2) >> 1)]));
        unsigned A3 = f2_to_h2u(__ldg(&x2[(size_t)(r0 + g + 8) * 64 + ((k0 + 8  + t4 * 2) >> 1)]));
        #pragma unroll
        for (int nt = 0; nt < 16; nt++) {
            unsigned b0 = *(const unsigned*)&g_WhT[(size_t)(nt * 8 + g) * D + k0 + t4 * 2];
            unsigned b1 = *(const unsigned*)&g_WhT[(size_t)(nt * 8 + g) * D + k0 + 8 + t4 * 2];
            asm volatile(
                "mma.sync.aligned.m16n8k16.row.col.f32.f16.f16.f32 "
                "{%0,%1,%2,%3}, {%4,%5,%6,%7}, {%8,%9}, {%0,%1,%2,%3};"
                : "+f"(acc[nt][0]), "+f"(acc[nt][1]), "+f"(acc[nt][2]), "+f"(acc[nt][3])
                : "r"(A0), "r"(A1), "r"(A2), "r"(A3), "r"(b0), "r"(b1));
        }
    }

    unsigned* tout = (unsigned*)g_t;       // half2 units; row = 64
    #pragma unroll
    for (int nt = 0; nt < 16; nt++) {
        __half2 lo = __floats2half2_rn(acc[nt][0], acc[nt][1]);
        __half2 hi = __floats2half2_rn(acc[nt][2], acc[nt][3]);
        tout[(size_t)(r0 + g)     * 64 + nt * 4 + t4] = *(unsigned*)&lo;
        tout[(size_t)(r0 + g + 8) * 64 + nt * 4 + t4] = *(unsigned*)&hi;
    }
}

// ---------------- aggregation passes (frozen R10 structure; uint16 indices) ----------
// MODE 0: y1 = (sum_neigh + self) * invd1
// MODE 1: y2 = (sum_neigh + self) * invd1 * outnorm
// MODE 2: out = innorm*sum_neigh + (innorm*sum outnorm[src])*bw + b3  (fp32 out)
template <int MODE>
__global__ __launch_bounds__(256) void k_agg(const __half* __restrict__ hin,
                                             __half* __restrict__ hout,
                                             const float* __restrict__ b3,
                                             float* __restrict__ out) {
    int t = blockIdx.x * 256 + threadIdx.x;
    int w = t >> 5;                       // global warp id
    int lane = threadIdx.x & 31;
    int sl = lane & 15;                   // sub-lane within half-warp
    int node = w * 2 + (lane >> 4);       // 2 nodes per warp
    if (node >= NN) return;

    const uint4* in8 = (const uint4*)hin; // 16B = 8 halves; row = 16 uint4

    float acc[8] = {0.f, 0.f, 0.f, 0.f, 0.f, 0.f, 0.f, 0.f};
    if (MODE < 2) add_h8(acc, __ldg(&in8[(size_t)node * 16 + sl]));
    float vs = 0.f;

    int end  = g_cnt[node];
    const unsigned short* mycol = g_colp + (size_t)node * PAD;
    int e = 0;

    while (e < end) {
        int cols[8];
        #pragma unroll
        for (int j = 0; j < 8; j++)
            cols[j] = (e + j < end) ? (int)__ldg(&mycol[e + j]) : -1;
        #pragma unroll
        for (int j = 0; j < 8; j++) {
            if (cols[j] >= 0) {
                uint4 v = __ldg(&in8[(size_t)cols[j] * 16 + sl]);
                add_h8(acc, v);
                if (MODE == 2) vs += g_outnorm[cols[j]];
            }
        }
        e += 8;
    }

    if (MODE < 2) {
        float sc = (MODE == 0) ? g_invd1[node] : g_invd1[node] * g_outnorm[node];
        uint4 u;
        __half2* h = (__half2*)&u;
        #pragma unroll
        for (int i = 0; i < 4; i++)
            h[i] = __floats2half2_rn(acc[2 * i] * sc, acc[2 * i + 1] * sc);
        ((uint4*)hout)[(size_t)node * 16 + sl] = u;
    } else {
        float sc = g_innorm[node];
        float vb = vs * sc;
        const float4* bw4 = (const float4*)g_bw;
        const float4* b34 = (const float4*)b3;
        float4 bwa = __ldg(&bw4[sl * 2]),     b3a = __ldg(&b34[sl * 2]);
        float4 bwb = __ldg(&bw4[sl * 2 + 1]), b3b = __ldg(&b34[sl * 2 + 1]);
        float4 o;
        float4* o4 = (float4*)out;
        o.x = acc[0] * sc + vb * bwa.x + b3a.x;
        o.y = acc[1] * sc + vb * bwa.y + b3a.y;
        o.z = acc[2] * sc + vb * bwa.z + b3a.z;
        o.w = acc[3] * sc + vb * bwa.w + b3a.w;
        o4[(size_t)node * 32 + sl * 2] = o;
        o.x = acc[4] * sc + vb * bwb.x + b3b.x;
        o.y = acc[5] * sc + vb * bwb.y + b3b.y;
        o.z = acc[6] * sc + vb * bwb.z + b3b.z;
        o.w = acc[7] * sc + vb * bwb.w + b3b.w;
        o4[(size_t)node * 32 + sl * 2 + 1] = o;
    }
}

// ---------------- launch ----------------
extern "C" void kernel_launch(void* const* d_in, const int* in_sizes, int n_in,
                              void* d_out, int out_size) {
    const float* x  = (const float*)d_in[0];
    const float* W1 = (const float*)d_in[1];
    const float* b1 = (const float*)d_in[2];
    const float* W2 = (const float*)d_in[3];
    const float* b2 = (const float*)d_in[4];
    const float* W3 = (const float*)d_in[5];
    const float* b3 = (const float*)d_in[6];
    const int* src  = (const int*)d_in[7];
    const int* dst  = (const int*)d_in[8];
    float* out = (float*)d_out;

    __half *tptr, *y1, *y2;
    void *dcnt, *dout_deg;
    cudaGetSymbolAddress((void**)&tptr, g_t);
    cudaGetSymbolAddress((void**)&y1, g_y1);
    cudaGetSymbolAddress((void**)&y2, g_y2);
    cudaGetSymbolAddress(&dcnt, g_cnt);
    cudaGetSymbolAddress(&dout_deg, g_deg_out);

    static cudaStream_t s1 = 0;
    static cudaEvent_t evA = 0, evB = 0;
    if (!s1) {
        cudaStreamCreateWithFlags(&s1, cudaStreamNonBlocking);
        cudaEventCreateWithFlags(&evA, cudaEventDisableTiming);
        cudaEventCreateWithFlags(&evB, cudaEventDisableTiming);
    }

    // ---- fork: padded-CSR build on worker stream s1 ----
    cudaEventRecord(evA, 0);
    cudaStreamWaitEvent(s1, evA, 0);
    cudaMemsetAsync(dcnt, 0, NN * sizeof(int), s1);
    cudaMemsetAsync(dout_deg, 0, NN * sizeof(int), s1);
    k_scatter<<<(NE / 2 + 255) / 256, 256, 0, s1>>>(src, dst);
    k_norms  <<<NB, 256, 0, s1>>>();
    cudaEventRecord(evB, s1);

    // ---- main stream: weights -> HMMA front GEMM ----
    k_wA<<<D + 1, 512>>>(W1, b1, W2, b2);
    k_wB<<<D + 1, 512>>>(W3);

    const int GEMM_WARPS = NN / 16;                    // 3125 (exact)
    const int GEMM_BLOCKS = (GEMM_WARPS + 7) / 8;      // 391
    k_gemm<<<GEMM_BLOCKS, 256>>>(x);

    // ---- join: agg passes need both GEMM output and adjacency ----
    cudaStreamWaitEvent(0, evB, 0);

    const int AGG_WARPS = (NN + 1) / 2;                    // 25000
    const int AGG_BLOCKS = (AGG_WARPS * 32 + 255) / 256;   // 3125
    k_agg<0><<<AGG_BLOCKS, 256>>>(tptr, y1, nullptr, nullptr);
    k_agg<1><<<AGG_BLOCKS, 256>>>(y1, y2, nullptr, nullptr);
    k_agg<2><<<AGG_BLOCKS, 256>>>(y2, nullptr, b3, out);
}

// round 14
// speedup vs baseline: 1.4587x; 1.4587x over previous
#include <cuda_runtime.h>
#include <cuda_fp16.h>
#include <math.h>

#define NN 50000
#define NE 800000
#define D 128
#define NB 196      // (NN + 255) / 256
#define PAD 64      // padded CSR slots per node; P(deg>=64)~1e-21 for Poisson(16)

// ---------------- device scratch (no allocations allowed) ----------------
__device__ int    g_cnt[NN];        // in-degree cursor -> final in-degree
__device__ int    g_deg_out[NN];
__device__ int    g_colp[NN * PAD]; // padded adjacency (sources per dst)
__device__ float  g_invd1[NN];
__device__ float  g_innorm[NN];
__device__ float  g_outnorm[NN];
__device__ __half g_t [NN * D];
__device__ __half g_y1[NN * D];
__device__ __half g_y2[NN * D];
__device__ float  g_Wt[D * D];
__device__ __half g_WhT[D * D];     // Wc transposed, fp16: [n][k]
__device__ float  g_bt[D];
__device__ float  g_bw[D];

__device__ __forceinline__ void add_h8(float* a, uint4 v) {
    __half2* h = (__half2*)&v;
    #pragma unroll
    for (int i = 0; i < 4; i++) {
        float2 f = __half22float2(h[i]);
        a[2 * i]     += f.x;
        a[2 * i + 1] += f.y;
    }
}
__device__ __forceinline__ unsigned f2_to_h2u(float2 f) {
    __half2 h = __floats2half2_rn(f.x, f.y);
    return *(unsigned*)&h;
}

// ---------------- graph preprocessing (worker stream) ----------------
// direct padded scatter + out-degree histogram (no hist/scan/rowptr passes)
__global__ void k_scatter(const int* __restrict__ src, const int* __restrict__ dst) {
    int i = blockIdx.x * blockDim.x + threadIdx.x;
    if (i < NE / 2) {
        int2 s = __ldg(&((const int2*)src)[i]);
        int2 d = __ldg(&((const int2*)dst)[i]);
        int p0 = atomicAdd(&g_cnt[d.x], 1);
        g_colp[d.x * PAD + p0] = s.x;
        int p1 = atomicAdd(&g_cnt[d.y], 1);
        g_colp[d.y * PAD + p1] = s.y;
        atomicAdd(&g_deg_out[s.x], 1);
        atomicAdd(&g_deg_out[s.y], 1);
    }
}

__global__ void k_norms() {
    int i = blockIdx.x * blockDim.x + threadIdx.x;
    if (i < NN) {
        int di = g_cnt[i], dq = g_deg_out[i];
        g_invd1[i]   = 1.0f / (float)(di + 1);
        g_innorm[i]  = rsqrtf((float)(di > 0 ? di : 1));
        g_outnorm[i] = rsqrtf((float)(dq > 0 ? dq : 1));
    }
}

// ---------------- fused weight precompute (k-split, 512 threads/block) ----------------
__global__ __launch_bounds__(512) void k_wA(const float* __restrict__ W1,
                                            const float* __restrict__ b1,
                                            const float* __restrict__ W2,
                                            const float* __restrict__ b2) {
    int r = blockIdx.x;
    int c = threadIdx.x & 127;
    int ks = threadIdx.x >> 7;            // 0..3
    __shared__ float arow[D];
    __shared__ float part[4][D];
    if (threadIdx.x < D) arow[threadIdx.x] = (r < D) ? W1[r * D + threadIdx.x] : b1[threadIdx.x];
    __syncthreads();
    int k0 = ks * 32;
    float a0 = 0.f, a1 = 0.f, a2 = 0.f, a3 = 0.f;
    #pragma unroll
    for (int k = 0; k < 32; k += 4) {
        a0 += arow[k0 + k + 0] * __ldg(&W2[(k0 + k + 0) * D + c]);
        a1 += arow[k0 + k + 1] * __ldg(&W2[(k0 + k + 1) * D + c]);
        a2 += arow[k0 + k + 2] * __ldg(&W2[(k0 + k + 2) * D + c]);
        a3 += arow[k0 + k + 3] * __ldg(&W2[(k0 + k + 3) * D + c]);
    }
    part[ks][c] = (a0 + a1) + (a2 + a3);
    __syncthreads();
    if (ks == 0) {
        float acc = (part[0][c] + part[1][c]) + (part[2][c] + part[3][c]);
        if (r < D) g_Wt[r * D + c] = acc;
        else       g_bt[c] = acc + b2[c];
    }
}
__global__ __launch_bounds__(512) void k_wB(const float* __restrict__ W3) {
    int r = blockIdx.x;
    int c = threadIdx.x & 127;
    int ks = threadIdx.x >> 7;
    __shared__ float arow[D];
    __shared__ float part[4][D];
    if (threadIdx.x < D) arow[threadIdx.x] = (r < D) ? g_Wt[r * D + threadIdx.x] : g_bt[threadIdx.x];
    __syncthreads();
    int k0 = ks * 32;
    float a0 = 0.f, a1 = 0.f, a2 = 0.f, a3 = 0.f;
    #pragma unroll
    for (int k = 0; k < 32; k += 4) {
        a0 += arow[k0 + k + 0] * __ldg(&W3[(k0 + k + 0) * D + c]);
        a1 += arow[k0 + k + 1] * __ldg(&W3[(k0 + k + 1) * D + c]);
        a2 += arow[k0 + k + 2] * __ldg(&W3[(k0 + k + 2) * D + c]);
        a3 += arow[k0 + k + 3] * __ldg(&W3[(k0 + k + 3) * D + c]);
    }
    part[ks][c] = (a0 + a1) + (a2 + a3);
    __syncthreads();
    if (ks == 0) {
        float acc = (part[0][c] + part[1][c]) + (part[2][c] + part[3][c]);
        if (r < D) g_WhT[c * D + r] = __float2half(acc);
        else       g_bw[c] = acc;
    }
}

// ---------------- front GEMM via HMMA: g_t = fp16(x) @ Wc  (fp32 accum, fp16 out) -------
__global__ __launch_bounds__(256) void k_gemm(const float* __restrict__ x) {
    int warp = (blockIdx.x * 256 + threadIdx.x) >> 5;
    int lane = threadIdx.x & 31;
    int r0 = warp * 16;
    if (r0 >= NN) return;
    int g = lane >> 2, t4 = lane & 3;

    const float2* x2 = (const float2*)x;   // row = 64 float2

    float acc[16][4];
    #pragma unroll
    for (int nt = 0; nt < 16; nt++)
        #pragma unroll
        for (int j = 0; j < 4; j++) acc[nt][j] = 0.f;

    #pragma unroll
    for (int kt = 0; kt < 8; kt++) {
        int k0 = kt * 16;
        unsigned A0 = f2_to_h2u(__ldg(&x2[(size_t)(r0 + g)     * 64 + ((k0      + t4 * 2) >> 1)]));
        unsigned A1 = f2_to_h2u(__ldg(&x2[(size_t)(r0 + g + 8) * 64 + ((k0      + t4 * 2) >> 1)]));
        unsigned A2 = f2_to_h2u(__ldg(&x2[(size_t)(r0 + g)     * 64 + ((k0 + 8  + t4 * 2) >> 1)]));
        unsigned A3 = f2_to_h2u(__ldg(&x2[(size_t)(r0 + g + 8) * 64 + ((k0 + 8  + t4 * 2) >> 1)]));
        #pragma unroll
        for (int nt = 0; nt < 16; nt++) {
            unsigned b0 = *(const unsigned*)&g_WhT[(size_t)(nt * 8 + g) * D + k0 + t4 * 2];
            unsigned b1 = *(const unsigned*)&g_WhT[(size_t)(nt * 8 + g) * D + k0 + 8 + t4 * 2];
            asm volatile(
                "mma.sync.aligned.m16n8k16.row.col.f32.f16.f16.f32 "
                "{%0,%1,%2,%3}, {%4,%5,%6,%7}, {%8,%9}, {%0,%1,%2,%3};"
                : "+f"(acc[nt][0]), "+f"(acc[nt][1]), "+f"(acc[nt][2]), "+f"(acc[nt][3])
                : "r"(A0), "r"(A1), "r"(A2), "r"(A3), "r"(b0), "r"(b1));
        }
    }

    unsigned* tout = (unsigned*)g_t;       // half2 units; row = 64
    #pragma unroll
    for (int nt = 0; nt < 16; nt++) {
        __half2 lo = __floats2half2_rn(acc[nt][0], acc[nt][1]);
        __half2 hi = __floats2half2_rn(acc[nt][2], acc[nt][3]);
        tout[(size_t)(r0 + g)     * 64 + nt * 4 + t4] = *(unsigned*)&lo;
        tout[(size_t)(r0 + g + 8) * 64 + nt * 4 + t4] = *(unsigned*)&hi;
    }
}

// ---------------- aggregation passes (frozen R5/R10 structure; padded adjacency) --------
// MODE 0: y1 = (sum_neigh + self) * invd1
// MODE 1: y2 = (sum_neigh + self) * invd1 * outnorm
// MODE 2: out = innorm*sum_neigh + (innorm*sum outnorm[src])*bw + b3  (fp32 out)
template <int MODE>
__global__ __launch_bounds__(256) void k_agg(const __half* __restrict__ hin,
                                             __half* __restrict__ hout,
                                             const float* __restrict__ b3,
                                             float* __restrict__ out) {
    int t = blockIdx.x * 256 + threadIdx.x;
    int w = t >> 5;                       // global warp id
    int lane = threadIdx.x & 31;
    int sl = lane & 15;                   // sub-lane within half-warp
    int node = w * 2 + (lane >> 4);       // 2 nodes per warp
    if (node >= NN) return;

    const uint4* in8 = (const uint4*)hin; // 16B = 8 halves; row = 16 uint4

    float acc[8] = {0.f, 0.f, 0.f, 0.f, 0.f, 0.f, 0.f, 0.f};
    if (MODE < 2) add_h8(acc, __ldg(&in8[(size_t)node * 16 + sl]));
    float vs = 0.f;

    int end  = g_cnt[node];
    const int* mycol = g_colp + (size_t)node * PAD;
    int e = 0;

    while (e < end) {
        int cols[8];
        #pragma unroll
        for (int j = 0; j < 8; j++)
            cols[j] = (e + j < end) ? __ldg(&mycol[e + j]) : -1;
        #pragma unroll
        for (int j = 0; j < 8; j++) {
            if (cols[j] >= 0) {
                uint4 v = __ldg(&in8[(size_t)cols[j] * 16 + sl]);
                add_h8(acc, v);
                if (MODE == 2) vs += g_outnorm[cols[j]];
            }
        }
        e += 8;
    }

    if (MODE < 2) {
        float sc = (MODE == 0) ? g_invd1[node] : g_invd1[node] * g_outnorm[node];
        uint4 u;
        __half2* h = (__half2*)&u;
        #pragma unroll
        for (int i = 0; i < 4; i++)
            h[i] = __floats2half2_rn(acc[2 * i] * sc, acc[2 * i + 1] * sc);
        ((uint4*)hout)[(size_t)node * 16 + sl] = u;
    } else {
        float sc = g_innorm[node];
        float vb = vs * sc;
        const float4* bw4 = (const float4*)g_bw;
        const float4* b34 = (const float4*)b3;
        float4 bwa = __ldg(&bw4[sl * 2]),     b3a = __ldg(&b34[sl * 2]);
        float4 bwb = __ldg(&bw4[sl * 2 + 1]), b3b = __ldg(&b34[sl * 2 + 1]);
        float4 o;
        float4* o4 = (float4*)out;
        o.x = acc[0] * sc + vb * bwa.x + b3a.x;
        o.y = acc[1] * sc + vb * bwa.y + b3a.y;
        o.z = acc[2] * sc + vb * bwa.z + b3a.z;
        o.w = acc[3] * sc + vb * bwa.w + b3a.w;
        o4[(size_t)node * 32 + sl * 2] = o;
        o.x = acc[4] * sc + vb * bwb.x + b3b.x;
        o.y = acc[5] * sc + vb * bwb.y + b3b.y;
        o.z = acc[6] * sc + vb * bwb.z + b3b.z;
        o.w = acc[7] * sc + vb * bwb.w + b3b.w;
        o4[(size_t)node * 32 + sl * 2 + 1] = o;
    }
}

// ---------------- launch ----------------
extern "C" void kernel_launch(void* const* d_in, const int* in_sizes, int n_in,
                              void* d_out, int out_size) {
    const float* x  = (const float*)d_in[0];
    const float* W1 = (const float*)d_in[1];
    const float* b1 = (const float*)d_in[2];
    const float* W2 = (const float*)d_in[3];
    const float* b2 = (const float*)d_in[4];
    const float* W3 = (const float*)d_in[5];
    const float* b3 = (const float*)d_in[6];
    const int* src  = (const int*)d_in[7];
    const int* dst  = (const int*)d_in[8];
    float* out = (float*)d_out;

    __half *tptr, *y1, *y2;
    void *dcnt, *dout_deg;
    cudaGetSymbolAddress((void**)&tptr, g_t);
    cudaGetSymbolAddress((void**)&y1, g_y1);
    cudaGetSymbolAddress((void**)&y2, g_y2);
    cudaGetSymbolAddress(&dcnt, g_cnt);
    cudaGetSymbolAddress(&dout_deg, g_deg_out);

    static cudaStream_t s1 = 0;
    static cudaEvent_t evA = 0, evB = 0;
    if (!s1) {
        cudaStreamCreateWithFlags(&s1, cudaStreamNonBlocking);
        cudaEventCreateWithFlags(&evA, cudaEventDisableTiming);
        cudaEventCreateWithFlags(&evB, cudaEventDisableTiming);
    }

    // ---- fork: padded-CSR build on worker stream s1 ----
    cudaEventRecord(evA, 0);
    cudaStreamWaitEvent(s1, evA, 0);
    cudaMemsetAsync(dcnt, 0, NN * sizeof(int), s1);
    cudaMemsetAsync(dout_deg, 0, NN * sizeof(int), s1);
    k_scatter<<<(NE / 2 + 255) / 256, 256, 0, s1>>>(src, dst);
    k_norms  <<<NB, 256, 0, s1>>>();
    cudaEventRecord(evB, s1);

    // ---- main stream: weights -> HMMA front GEMM ----
    k_wA<<<D + 1, 512>>>(W1, b1, W2, b2);
    k_wB<<<D + 1, 512>>>(W3);

    const int GEMM_WARPS = NN / 16;                    // 3125 (exact)
    const int GEMM_BLOCKS = (GEMM_WARPS + 7) / 8;      // 391
    k_gemm<<<GEMM_BLOCKS, 256>>>(x);

    // ---- join: agg passes need both GEMM output and adjacency ----
    cudaStreamWaitEvent(0, evB, 0);

    const int AGG_WARPS = (NN + 1) / 2;                    // 25000
    const int AGG_BLOCKS = (AGG_WARPS * 32 + 255) / 256;   // 3125
    k_agg<0><<<AGG_BLOCKS, 256>>>(tptr, y1, nullptr, nullptr);
    k_agg<1><<<AGG_BLOCKS, 256>>>(y1, y2, nullptr, nullptr);
    k_agg<2><<<AGG_BLOCKS, 256>>>(y2, nullptr, b3, out);
}

// round 16
// speedup vs baseline: 1.4934x; 1.0238x over previous
#include <cuda_runtime.h>
#include <cuda_fp16.h>
#include <math.h>

#define NN 50000
#define NE 800000
#define D 128
#define NB 196      // (NN + 255) / 256
#define PAD 64      // padded CSR slots per node; P(deg>=64)~1e-21 for Poisson(16)

// ---------------- device scratch (no allocations allowed) ----------------
__device__ int    g_cnt[NN];        // in-degree cursor -> final in-degree
__device__ int    g_deg_out[NN];
__device__ int    g_colp[NN * PAD]; // padded adjacency (sources per dst)
__device__ float  g_invd1[NN];
__device__ float  g_innorm[NN];
__device__ float  g_outnorm[NN];
__device__ __half g_t [NN * D];
__device__ __half g_y1[NN * D];
__device__ __half g_y2[NN * D];
__device__ __half g_WhT[D * D];     // Wc transposed, fp16: [n][k]
__device__ float  g_bw[D];
__device__ float  g_sink;           // k_warm reduction sink (never written in practice)

__device__ __forceinline__ void add_h8(float* a, uint4 v) {
    __half2* h = (__half2*)&v;
    #pragma unroll
    for (int i = 0; i < 4; i++) {
        float2 f = __half22float2(h[i]);
        a[2 * i]     += f.x;
        a[2 * i + 1] += f.y;
    }
}
__device__ __forceinline__ unsigned f2_to_h2u(float2 f) {
    __half2 h = __floats2half2_rn(f.x, f.y);
    return *(unsigned*)&h;
}

// ---------------- graph preprocessing (worker stream) ----------------
// direct padded scatter + out-degree histogram (no hist/scan/rowptr passes)
__global__ void k_scatter(const int* __restrict__ src, const int* __restrict__ dst) {
    int i = blockIdx.x * blockDim.x + threadIdx.x;
    if (i < NE / 2) {
        int2 s = __ldg(&((const int2*)src)[i]);
        int2 d = __ldg(&((const int2*)dst)[i]);
        int p0 = atomicAdd(&g_cnt[d.x], 1);
        g_colp[d.x * PAD + p0] = s.x;
        int p1 = atomicAdd(&g_cnt[d.y], 1);
        g_colp[d.y * PAD + p1] = s.y;
        atomicAdd(&g_deg_out[s.x], 1);
        atomicAdd(&g_deg_out[s.y], 1);
    }
}

__global__ void k_norms() {
    int i = blockIdx.x * blockDim.x + threadIdx.x;
    if (i < NN) {
        int di = g_cnt[i], dq = g_deg_out[i];
        g_invd1[i]   = 1.0f / (float)(di + 1);
        g_innorm[i]  = rsqrtf((float)(di > 0 ? di : 1));
        g_outnorm[i] = rsqrtf((float)(dq > 0 ? dq : 1));
    }
}

// ---------------- L2 warm-up for W3 (runs concurrently with k_wAB phase 1) ----------
__global__ void k_warm(const float* __restrict__ W3) {
    int i = blockIdx.x * blockDim.x + threadIdx.x;
    float v = 0.f;
    if (i < D * D / 4) {
        float4 t = __ldg(&((const float4*)W3)[i]);
        v = t.x + t.y + t.z + t.w;
    }
    if (v == 1234567.891f) g_sink = v;    // never true; defeats DCE
}

// ---------------- fused weight precompute: Wc = (W1@W2)@W3 in ONE kernel ----------------
// block r: phase 1 computes Wt_row = (W1[r] or b1) @ W2 (+b2) into smem;
//          phase 2 computes Wc[r] = Wt_row @ W3, writes g_WhT (fp16, transposed) / g_bw.
__global__ __launch_bounds__(512) void k_wAB(const float* __restrict__ W1,
                                             const float* __restrict__ b1,
                                             const float* __restrict__ W2,
                                             const float* __restrict__ b2,
                                             const float* __restrict__ W3) {
    int r = blockIdx.x;                   // 0..D (row D = bias row)
    int c = threadIdx.x & 127;
    int ks = threadIdx.x >> 7;            // 0..3
    __shared__ float arow[D];
    __shared__ float part[4][D];
    __shared__ float wt[D];

    // ---- phase 1: wt = (W1[r] | b1) @ W2  (+ b2 on bias row) ----
    if (threadIdx.x < D) arow[threadIdx.x] = (r < D) ? W1[r * D + threadIdx.x] : b1[threadIdx.x];
    __syncthreads();
    {
        int k0 = ks * 32;
        float a0 = 0.f, a1 = 0.f, a2 = 0.f, a3 = 0.f;
        #pragma unroll
        for (int k = 0; k < 32; k += 4) {
            a0 += arow[k0 + k + 0] * __ldg(&W2[(k0 + k + 0) * D + c]);
            a1 += arow[k0 + k + 1] * __ldg(&W2[(k0 + k + 1) * D + c]);
            a2 += arow[k0 + k + 2] * __ldg(&W2[(k0 + k + 2) * D + c]);
            a3 += arow[k0 + k + 3] * __ldg(&W2[(k0 + k + 3) * D + c]);
        }
        part[ks][c] = (a0 + a1) + (a2 + a3);
    }
    __syncthreads();
    if (ks == 0) {
        float acc = (part[0][c] + part[1][c]) + (part[2][c] + part[3][c]);
        wt[c] = (r < D) ? acc : acc + b2[c];
    }
    __syncthreads();

    // ---- phase 2: out = wt @ W3 ----
    {
        int k0 = ks * 32;
        float a0 = 0.f, a1 = 0.f, a2 = 0.f, a3 = 0.f;
        #pragma unroll
        for (int k = 0; k < 32; k += 4) {
            a0 += wt[k0 + k + 0] * __ldg(&W3[(k0 + k + 0) * D + c]);
            a1 += wt[k0 + k + 1] * __ldg(&W3[(k0 + k + 1) * D + c]);
            a2 += wt[k0 + k + 2] * __ldg(&W3[(k0 + k + 2) * D + c]);
            a3 += wt[k0 + k + 3] * __ldg(&W3[(k0 + k + 3) * D + c]);
        }
        part[ks][c] = (a0 + a1) + (a2 + a3);
    }
    __syncthreads();
    if (ks == 0) {
        float acc = (part[0][c] + part[1][c]) + (part[2][c] + part[3][c]);
        if (r < D) g_WhT[c * D + r] = __float2half(acc);
        else       g_bw[c] = acc;
    }
}

// ---------------- front GEMM via HMMA: g_t = fp16(x) @ Wc  (fp32 accum, fp16 out) -------
__global__ __launch_bounds__(256) void k_gemm(const float* __restrict__ x) {
    int warp = (blockIdx.x * 256 + threadIdx.x) >> 5;
    int lane = threadIdx.x & 31;
    int r0 = warp * 16;
    if (r0 >= NN) return;
    int g = lane >> 2, t4 = lane & 3;

    const float2* x2 = (const float2*)x;   // row = 64 float2

    float acc[16][4];
    #pragma unroll
    for (int nt = 0; nt < 16; nt++)
        #pragma unroll
        for (int j = 0; j < 4; j++) acc[nt][j] = 0.f;

    #pragma unroll
    for (int kt = 0; kt < 8; kt++) {
        int k0 = kt * 16;
        unsigned A0 = f2_to_h2u(__ldg(&x2[(size_t)(r0 + g)     * 64 + ((k0      + t4 * 2) >> 1)]));
        unsigned A1 = f2_to_h2u(__ldg(&x2[(size_t)(r0 + g + 8) * 64 + ((k0      + t4 * 2) >> 1)]));
        unsigned A2 = f2_to_h2u(__ldg(&x2[(size_t)(r0 + g)     * 64 + ((k0 + 8  + t4 * 2) >> 1)]));
        unsigned A3 = f2_to_h2u(__ldg(&x2[(size_t)(r0 + g + 8) * 64 + ((k0 + 8  + t4 * 2) >> 1)]));
        #pragma unroll
        for (int nt = 0; nt < 16; nt++) {
            unsigned b0 = *(const unsigned*)&g_WhT[(size_t)(nt * 8 + g) * D + k0 + t4 * 2];
            unsigned b1 = *(const unsigned*)&g_WhT[(size_t)(nt * 8 + g) * D + k0 + 8 + t4 * 2];
            asm volatile(
                "mma.sync.aligned.m16n8k16.row.col.f32.f16.f16.f32 "
                "{%0,%1,%2,%3}, {%4,%5,%6,%7}, {%8,%9}, {%0,%1,%2,%3};"
                : "+f"(acc[nt][0]), "+f"(acc[nt][1]), "+f"(acc[nt][2]), "+f"(acc[nt][3])
                : "r"(A0), "r"(A1), "r"(A2), "r"(A3), "r"(b0), "r"(b1));
        }
    }

    unsigned* tout = (unsigned*)g_t;       // half2 units; row = 64
    #pragma unroll
    for (int nt = 0; nt < 16; nt++) {
        __half2 lo = __floats2half2_rn(acc[nt][0], acc[nt][1]);
        __half2 hi = __floats2half2_rn(acc[nt][2], acc[nt][3]);
        tout[(size_t)(r0 + g)     * 64 + nt * 4 + t4] = *(unsigned*)&lo;
        tout[(size_t)(r0 + g + 8) * 64 + nt * 4 + t4] = *(unsigned*)&hi;
    }
}

// ---------------- aggregation passes (frozen R5/R10 structure; padded adjacency) --------
// MODE 0: y1 = (sum_neigh + self) * invd1
// MODE 1: y2 = (sum_neigh + self) * invd1 * outnorm
// MODE 2: out = innorm*sum_neigh + (innorm*sum outnorm[src])*bw + b3  (fp32 out)
template <int MODE>
__global__ __launch_bounds__(256) void k_agg(const __half* __restrict__ hin,
                                             __half* __restrict__ hout,
                                             const float* __restrict__ b3,
                                             float* __restrict__ out) {
    int t = blockIdx.x * 256 + threadIdx.x;
    int w = t >> 5;                       // global warp id
    int lane = threadIdx.x & 31;
    int sl = lane & 15;                   // sub-lane within half-warp
    int node = w * 2 + (lane >> 4);       // 2 nodes per warp
    if (node >= NN) return;

    const uint4* in8 = (const uint4*)hin; // 16B = 8 halves; row = 16 uint4

    float acc[8] = {0.f, 0.f, 0.f, 0.f, 0.f, 0.f, 0.f, 0.f};
    if (MODE < 2) add_h8(acc, __ldg(&in8[(size_t)node * 16 + sl]));
    float vs = 0.f;

    int end  = g_cnt[node];
    const int* mycol = g_colp + (size_t)node * PAD;
    int e = 0;

    while (e < end) {
        int cols[8];
        #pragma unroll
        for (int j = 0; j < 8; j++)
            cols[j] = (e + j < end) ? __ldg(&mycol[e + j]) : -1;
        #pragma unroll
        for (int j = 0; j < 8; j++) {
            if (cols[j] >= 0) {
                uint4 v = __ldg(&in8[(size_t)cols[j] * 16 + sl]);
                add_h8(acc, v);
                if (MODE == 2) vs += g_outnorm[cols[j]];
            }
        }
        e += 8;
    }

    if (MODE < 2) {
        float sc = (MODE == 0) ? g_invd1[node] : g_invd1[node] * g_outnorm[node];
        uint4 u;
        __half2* h = (__half2*)&u;
        #pragma unroll
        for (int i = 0; i < 4; i++)
            h[i] = __floats2half2_rn(acc[2 * i] * sc, acc[2 * i + 1] * sc);
        ((uint4*)hout)[(size_t)node * 16 + sl] = u;
    } else {
        float sc = g_innorm[node];
        float vb = vs * sc;
        const float4* bw4 = (const float4*)g_bw;
        const float4* b34 = (const float4*)b3;
        float4 bwa = __ldg(&bw4[sl * 2]),     b3a = __ldg(&b34[sl * 2]);
        float4 bwb = __ldg(&bw4[sl * 2 + 1]), b3b = __ldg(&b34[sl * 2 + 1]);
        float4 o;
        float4* o4 = (float4*)out;
        o.x = acc[0] * sc + vb * bwa.x + b3a.x;
        o.y = acc[1] * sc + vb * bwa.y + b3a.y;
        o.z = acc[2] * sc + vb * bwa.z + b3a.z;
        o.w = acc[3] * sc + vb * bwa.w + b3a.w;
        o4[(size_t)node * 32 + sl * 2] = o;
        o.x = acc[4] * sc + vb * bwb.x + b3b.x;
        o.y = acc[5] * sc + vb * bwb.y + b3b.y;
        o.z = acc[6] * sc + vb * bwb.z + b3b.z;
        o.w = acc[7] * sc + vb * bwb.w + b3b.w;
        o4[(size_t)node * 32 + sl * 2 + 1] = o;
    }
}

// ---------------- launch ----------------
extern "C" void kernel_launch(void* const* d_in, const int* in_sizes, int n_in,
                              void* d_out, int out_size) {
    const float* x  = (const float*)d_in[0];
    const float* W1 = (const float*)d_in[1];
    const float* b1 = (const float*)d_in[2];
    const float* W2 = (const float*)d_in[3];
    const float* b2 = (const float*)d_in[4];
    const float* W3 = (const float*)d_in[5];
    const float* b3 = (const float*)d_in[6];
    const int* src  = (const int*)d_in[7];
    const int* dst  = (const int*)d_in[8];
    float* out = (float*)d_out;

    __half *tptr, *y1, *y2;
    void *dcnt, *dout_deg;
    cudaGetSymbolAddress((void**)&tptr, g_t);
    cudaGetSymbolAddress((void**)&y1, g_y1);
    cudaGetSymbolAddress((void**)&y2, g_y2);
    cudaGetSymbolAddress(&dcnt, g_cnt);
    cudaGetSymbolAddress(&dout_deg, g_deg_out);

    static cudaStream_t s1 = 0, s2 = 0;
    static cudaEvent_t evA = 0, evB = 0, evW = 0;
    if (!s1) {
        cudaStreamCreateWithFlags(&s1, cudaStreamNonBlocking);
        cudaStreamCreateWithFlags(&s2, cudaStreamNonBlocking);
        cudaEventCreateWithFlags(&evA, cudaEventDisableTiming);
        cudaEventCreateWithFlags(&evB, cudaEventDisableTiming);
        cudaEventCreateWithFlags(&evW, cudaEventDisableTiming);
    }

    // ---- fork: padded-CSR build on worker stream s1; W3 warm-up on s2 ----
    cudaEventRecord(evA, 0);
    cudaStreamWaitEvent(s1, evA, 0);
    cudaStreamWaitEvent(s2, evA, 0);
    cudaMemsetAsync(dcnt, 0, NN * sizeof(int), s1);
    cudaMemsetAsync(dout_deg, 0, NN * sizeof(int), s1);
    k_scatter<<<(NE / 2 + 255) / 256, 256, 0, s1>>>(src, dst);
    k_norms  <<<NB, 256, 0, s1>>>();
    cudaEventRecord(evB, s1);

    k_warm<<<(D * D / 4 + 255) / 256, 256, 0, s2>>>(W3);   // pull W3 into L2
    cudaEventRecord(evW, s2);

    // ---- main stream: fused weight chain -> (join s2) -> HMMA front GEMM ----
    k_wAB<<<D + 1, 512>>>(W1, b1, W2, b2, W3);
    cudaStreamWaitEvent(0, evW, 0);      // join s2 (k_warm done long before k_wAB)

    const int GEMM_WARPS = NN / 16;                    // 3125 (exact)
    const int GEMM_BLOCKS = (GEMM_WARPS + 7) / 8;      // 391
    k_gemm<<<GEMM_BLOCKS, 256>>>(x);

    // ---- join: agg passes need both GEMM output and adjacency ----
    cudaStreamWaitEvent(0, evB, 0);

    const int AGG_WARPS = (NN + 1) / 2;                    // 25000
    const int AGG_BLOCKS = (AGG_WARPS * 32 + 255) / 256;   // 3125
    k_agg<0><<<AGG_BLOCKS, 256>>>(tptr, y1, nullptr, nullptr);
    k_agg<1><<<AGG_BLOCKS, 256>>>(y1, y2, nullptr, nullptr);
    k_agg<2><<<AGG_BLOCKS, 256>>>(y2, nullptr, b3, out);
}